// round 16
// baseline (speedup 1.0000x reference)
#include <cuda_runtime.h>
#include <cuda_bf16.h>
#include <math.h>

#define TT 2048
#define DD 1024
#define NH 8
#define HD 128
#define KC 4
#define CH 128
#define NCHUNK (TT / CH)
#define BM 128
#define BN 128
#define BKK 32
#define ATT_SCALE 0.08838834764831845f  // 1/sqrt(128)

#define PLD ((size_t)TT * DD)
#define PLQ ((size_t)NH * TT * HD)
#define PLT ((size_t)NH * TT * TT)
#define PLW ((size_t)DD * 4 * DD)
#define PLO ((size_t)DD * DD)

// smem stage layout (bytes)
#define NN_AH 0
#define NN_AL 10240
#define NN_BH 20480
#define NN_BL 29184
#define NN_STAGE_B 37888
#define SMNN (3 * NN_STAGE_B)          // 3-stage pipeline
#define NT_AH 0
#define NT_AL 10240
#define NT_BH 20480
#define NT_BL 30720
#define NT_STAGE_B 40960
#define SMNT (2 * NT_STAGE_B)

// ---------------- scratch (device globals) ----------------------------------
__device__ float g_raw[(size_t)TT * 4 * DD];   // projections; later PV partials
__device__ __nv_bfloat16 g_xs[2 * PLD];
__device__ __nv_bfloat16 g_W4s[2 * PLW];
__device__ __nv_bfloat16 g_Wos[2 * PLO];
__device__ __nv_bfloat16 g_qs[2 * PLQ];
__device__ __nv_bfloat16 g_ks[2 * PLQ];
__device__ __nv_bfloat16 g_vs[2 * PLQ];
__device__ __nv_bfloat16 g_ws2[2 * PLQ];
__device__ __nv_bfloat16 g_QWs[2 * PLT];
__device__ __nv_bfloat16 g_Mws[2 * PLT];
__device__ __nv_bfloat16 g_Ps[2 * PLT];
__device__ __nv_bfloat16 g_bms[2 * PLT];
__device__ __nv_bfloat16 g_bts[2 * PLT];
__device__ __nv_bfloat16 g_Os[2 * PLD];
__device__ float g_A[PLT];
__device__ float g_bm[PLT];
__device__ float g_beta[NH * TT];
__device__ float g_gpre[NH * TT];
__device__ float g_G[NH * TT];

// ---------------- helpers ----------------------------------------------------
__device__ __forceinline__ unsigned smem_u32(const void* p) {
    return (unsigned)__cvta_generic_to_shared(p);
}
__device__ __forceinline__ void ldm_x4(unsigned addr, unsigned* r) {
    asm volatile("ldmatrix.sync.aligned.m8n8.x4.shared.b16 {%0,%1,%2,%3}, [%4];"
        : "=r"(r[0]), "=r"(r[1]), "=r"(r[2]), "=r"(r[3]) : "r"(addr));
}
__device__ __forceinline__ void ldm_x4t(unsigned addr, unsigned* r) {
    asm volatile("ldmatrix.sync.aligned.m8n8.x4.trans.shared.b16 {%0,%1,%2,%3}, [%4];"
        : "=r"(r[0]), "=r"(r[1]), "=r"(r[2]), "=r"(r[3]) : "r"(addr));
}
__device__ __forceinline__ void mma_bf16(float* c, const unsigned* a, unsigned b0, unsigned b1) {
    asm volatile(
        "mma.sync.aligned.m16n8k16.row.col.f32.bf16.bf16.f32 "
        "{%0,%1,%2,%3}, {%4,%5,%6,%7}, {%8,%9}, {%0,%1,%2,%3};"
        : "+f"(c[0]), "+f"(c[1]), "+f"(c[2]), "+f"(c[3])
        : "r"(a[0]), "r"(a[1]), "r"(a[2]), "r"(a[3]), "r"(b0), "r"(b1));
}
__device__ __forceinline__ void cp16(unsigned dst, const void* src) {
    asm volatile("cp.async.cg.shared.global [%0], [%1], 16;" :: "r"(dst), "l"(src));
}
#define CP_COMMIT() asm volatile("cp.async.commit_group;" ::: "memory")
__device__ __forceinline__ void cp_wait0() { asm volatile("cp.async.wait_group 0;" ::: "memory"); }
__device__ __forceinline__ void cp_wait1() { asm volatile("cp.async.wait_group 1;" ::: "memory"); }

// pack two floats into bf16x2 hi + lo planes
__device__ __forceinline__ void split2pair(float a, float b, unsigned& h, unsigned& l) {
    __nv_bfloat16 ha = __float2bfloat16(a), hb = __float2bfloat16(b);
    float ra = a - __bfloat162float(ha), rb = b - __bfloat162float(hb);
    __nv_bfloat162 H(ha, hb);
    __nv_bfloat162 L(__float2bfloat16(ra), __float2bfloat16(rb));
    h = *reinterpret_cast<unsigned*>(&H);
    l = *reinterpret_cast<unsigned*>(&L);
}

// ---------------- NN GEMM on bf16 hi/lo planes, 3-stage cp.async ------------
// flags: 1 = subtract; 2 = triangular; 4 = causal K; 8 = split-K PV.
// yOfs shifts the row-tile index (row-half pipelining). Triangular mode
// processes y in descending order (long-K tiles first).
__global__ __launch_bounds__(256, 2) void mma_nn_b(
    const __nv_bfloat16* __restrict__ AH, const __nv_bfloat16* __restrict__ AL,
    const __nv_bfloat16* __restrict__ BH, const __nv_bfloat16* __restrict__ BL,
    float* __restrict__ C,
    int K, int lda, int ldb, int ldc,
    long long sA, long long sB, long long sC, int flags, int yOfs)
{
    const int bx = blockIdx.x;
    int by;
    if (flags & 2) {
        by = yOfs + (gridDim.y - 1 - blockIdx.y);   // descending
        if (bx > by) return;
    } else {
        by = yOfs + blockIdx.y;
    }
    const int rowBase = by * BM, colBase = bx * BN;
    int kBeg, kEnd;
    if (flags & 8) {
        int h = blockIdx.z & 7, sp = blockIdx.z >> 3;
        AH += (long long)h * sA; AL += (long long)h * sA;
        BH += (long long)h * sB; BL += (long long)h * sB;
        C += (size_t)sp * TT * DD + (long long)h * sC;
        kBeg = sp * 512;
        kEnd = min(min(K, rowBase + BM), kBeg + 512);
    } else {
        AH += (long long)blockIdx.z * sA; AL += (long long)blockIdx.z * sA;
        BH += (long long)blockIdx.z * sB; BL += (long long)blockIdx.z * sB;
        C += (long long)blockIdx.z * sC;
        kBeg = (flags & 2) ? colBase : 0;
        kEnd = (flags & 6) ? min(K, rowBase + BM) : K;
    }
    const int nT = (kEnd > kBeg) ? (kEnd - kBeg) / BKK : 0;
    if (nT <= 0 && (flags & 1)) return;

    extern __shared__ __align__(16) char smch[];
    const unsigned smb = smem_u32(smch);

    const int tid = threadIdx.x, lane = tid & 31, wid = tid >> 5;
    const int wr = wid & 3, wc = wid >> 2;
    const int g = lane >> 2, t4 = lane & 3;
    const int ar = tid >> 2, aq = (tid & 3) * 8;
    const int br = tid >> 4, bq = (tid & 15) * 8;

    float acc[2][8][4] = {};

    auto issue = [&](int it) {
        const int kk = kBeg + it * BKK;
        const unsigned st = smb + (it % 3) * NN_STAGE_B;
        cp16(st + NN_AH + ar * 80 + aq * 2, AH + (size_t)(rowBase + ar) * lda + kk + aq);
        cp16(st + NN_AH + (ar + 64) * 80 + aq * 2, AH + (size_t)(rowBase + ar + 64) * lda + kk + aq);
        cp16(st + NN_AL + ar * 80 + aq * 2, AL + (size_t)(rowBase + ar) * lda + kk + aq);
        cp16(st + NN_AL + (ar + 64) * 80 + aq * 2, AL + (size_t)(rowBase + ar + 64) * lda + kk + aq);
        cp16(st + NN_BH + br * 272 + bq * 2, BH + (size_t)(kk + br) * ldb + colBase + bq);
        cp16(st + NN_BH + (br + 16) * 272 + bq * 2, BH + (size_t)(kk + br + 16) * ldb + colBase + bq);
        cp16(st + NN_BL + br * 272 + bq * 2, BL + (size_t)(kk + br) * ldb + colBase + bq);
        cp16(st + NN_BL + (br + 16) * 272 + bq * 2, BL + (size_t)(kk + br + 16) * ldb + colBase + bq);
        CP_COMMIT();
    };

    if (nT > 0) issue(0);
    if (nT > 1) issue(1);

    for (int i = 0; i < nT; i++) {
        if (i + 1 < nT) cp_wait1(); else cp_wait0();
        __syncthreads();
        if (i + 2 < nT) issue(i + 2);
        const unsigned st = smb + (i % 3) * NN_STAGE_B;
#pragma unroll
        for (int k16 = 0; k16 < BKK; k16 += 16) {
            unsigned aH0[4], aH1[4], aL0[4], aL1[4];
            const int rA = wr * 32 + (lane & 7) + ((lane >> 3) & 1) * 8;
            const int cA = k16 + (lane >> 4) * 8;
            ldm_x4(st + NN_AH + rA * 80 + cA * 2, aH0);
            ldm_x4(st + NN_AH + (rA + 16) * 80 + cA * 2, aH1);
            ldm_x4(st + NN_AL + rA * 80 + cA * 2, aL0);
            ldm_x4(st + NN_AL + (rA + 16) * 80 + cA * 2, aL1);
            const int rB = k16 + (lane & 7) + ((lane >> 3) & 1) * 8;
            const int cB = wc * 64 + (lane >> 4) * 8;
#pragma unroll
            for (int nq = 0; nq < 4; nq++) {
                unsigned bH[4], bL[4];
                ldm_x4t(st + NN_BH + rB * 272 + (cB + nq * 16) * 2, bH);
                ldm_x4t(st + NN_BL + rB * 272 + (cB + nq * 16) * 2, bL);
#pragma unroll
                for (int sub = 0; sub < 2; sub++) {
                    const int nt = nq * 2 + sub;
                    unsigned b0h = bH[sub * 2], b1h = bH[sub * 2 + 1];
                    unsigned b0l = bL[sub * 2], b1l = bL[sub * 2 + 1];
                    mma_bf16(acc[0][nt], aH0, b0h, b1h);
                    mma_bf16(acc[0][nt], aH0, b0l, b1l);
                    mma_bf16(acc[0][nt], aL0, b0h, b1h);
                    mma_bf16(acc[1][nt], aH1, b0h, b1h);
                    mma_bf16(acc[1][nt], aH1, b0l, b1l);
                    mma_bf16(acc[1][nt], aL1, b0h, b1h);
                }
            }
        }
    }

#pragma unroll
    for (int mt = 0; mt < 2; mt++) {
#pragma unroll
        for (int nt = 0; nt < 8; nt++) {
            int r0 = rowBase + wr * 32 + mt * 16 + g;
            int c0 = colBase + wc * 64 + nt * 8 + t4 * 2;
            float* p0 = C + (long long)r0 * ldc + c0;
            float* p1 = C + (long long)(r0 + 8) * ldc + c0;
            if (flags & 1) {
                float2 v0 = *(float2*)p0;
                v0.x -= acc[mt][nt][0]; v0.y -= acc[mt][nt][1];
                *(float2*)p0 = v0;
                float2 v1 = *(float2*)p1;
                v1.x -= acc[mt][nt][2]; v1.y -= acc[mt][nt][3];
                *(float2*)p1 = v1;
            } else {
                float2 v0 = {acc[mt][nt][0], acc[mt][nt][1]};
                float2 v1 = {acc[mt][nt][2], acc[mt][nt][3]};
                *(float2*)p0 = v0;
                *(float2*)p1 = v1;
            }
        }
    }
}

// ---------------- NT GEMM (A @ B^T) on bf16 planes, [T,128] heads -----------
// modes: 0 = QK^T -> f32; 1 = tril(QW^T,0) -> planes; 2 = strict lower -> f32
// (upper tiles zero-filled); 3 = strict-lower * beta[col] -> planes.
__global__ __launch_bounds__(256, 2) void mma_nt_b(
    const __nv_bfloat16* __restrict__ AH, const __nv_bfloat16* __restrict__ AL,
    const __nv_bfloat16* __restrict__ BH, const __nv_bfloat16* __restrict__ BL,
    float* __restrict__ Cf, __nv_bfloat16* __restrict__ CpH, __nv_bfloat16* __restrict__ CpL,
    const float* __restrict__ betaArr, int mode)
{
    const int bx = blockIdx.x, by = blockIdx.y, h = blockIdx.z;
    const int rowBase = by * BM, colBase = bx * BN;
    const int tid = threadIdx.x, lane = tid & 31, wid = tid >> 5;
    if (bx > by) {
        if (mode == 2) {
            float* Ch = Cf + (size_t)h * TT * TT;
            float4 z = {0.f, 0.f, 0.f, 0.f};
#pragma unroll
            for (int i = 0; i < 16; i++) {
                int fid = i * 256 + tid;
                int r = fid >> 5, c = (fid & 31) * 4;
                *(float4*)(Ch + (size_t)(rowBase + r) * TT + colBase + c) = z;
            }
        }
        return;
    }
    const size_t hq = (size_t)h * TT * HD;
    AH += hq; AL += hq; BH += hq; BL += hq;

    extern __shared__ __align__(16) char smch[];
    const unsigned smb = smem_u32(smch);

    const int wr = wid & 3, wc = wid >> 2;
    const int g = lane >> 2, t4 = lane & 3;
    const int ar = tid >> 2, aq = (tid & 3) * 8;

    float acc[2][8][4] = {};

    auto issue = [&](int it) {
        const int kk = it * BKK;
        const unsigned st = smb + (it & 1) * NT_STAGE_B;
        cp16(st + NT_AH + ar * 80 + aq * 2, AH + (size_t)(rowBase + ar) * HD + kk + aq);
        cp16(st + NT_AH + (ar + 64) * 80 + aq * 2, AH + (size_t)(rowBase + ar + 64) * HD + kk + aq);
        cp16(st + NT_AL + ar * 80 + aq * 2, AL + (size_t)(rowBase + ar) * HD + kk + aq);
        cp16(st + NT_AL + (ar + 64) * 80 + aq * 2, AL + (size_t)(rowBase + ar + 64) * HD + kk + aq);
        cp16(st + NT_BH + ar * 80 + aq * 2, BH + (size_t)(colBase + ar) * HD + kk + aq);
        cp16(st + NT_BH + (ar + 64) * 80 + aq * 2, BH + (size_t)(colBase + ar + 64) * HD + kk + aq);
        cp16(st + NT_BL + ar * 80 + aq * 2, BL + (size_t)(colBase + ar) * HD + kk + aq);
        cp16(st + NT_BL + (ar + 64) * 80 + aq * 2, BL + (size_t)(colBase + ar + 64) * HD + kk + aq);
        CP_COMMIT();
    };

    const int nT = HD / BKK;   // 4
    issue(0);
    issue(1);

    for (int i = 0; i < nT; i++) {
        if (i + 1 < nT) cp_wait1(); else cp_wait0();
        __syncthreads();
        const unsigned st = smb + (i & 1) * NT_STAGE_B;
#pragma unroll
        for (int k16 = 0; k16 < BKK; k16 += 16) {
            unsigned aH0[4], aH1[4], aL0[4], aL1[4];
            const int rA = wr * 32 + (lane & 7) + ((lane >> 3) & 1) * 8;
            const int cA = k16 + (lane >> 4) * 8;
            ldm_x4(st + NT_AH + rA * 80 + cA * 2, aH0);
            ldm_x4(st + NT_AH + (rA + 16) * 80 + cA * 2, aH1);
            ldm_x4(st + NT_AL + rA * 80 + cA * 2, aL0);
            ldm_x4(st + NT_AL + (rA + 16) * 80 + cA * 2, aL1);
            const int rBn = wc * 64 + ((lane >> 4) & 1) * 8 + (lane & 7);
            const int cBn = k16 + ((lane >> 3) & 1) * 8;
#pragma unroll
            for (int nq = 0; nq < 4; nq++) {
                unsigned bH[4], bL[4];
                ldm_x4(st + NT_BH + (rBn + nq * 16) * 80 + cBn * 2, bH);
                ldm_x4(st + NT_BL + (rBn + nq * 16) * 80 + cBn * 2, bL);
#pragma unroll
                for (int sub = 0; sub < 2; sub++) {
                    const int nt = nq * 2 + sub;
                    unsigned b0h = bH[sub * 2], b1h = bH[sub * 2 + 1];
                    unsigned b0l = bL[sub * 2], b1l = bL[sub * 2 + 1];
                    mma_bf16(acc[0][nt], aH0, b0h, b1h);
                    mma_bf16(acc[0][nt], aH0, b0l, b1l);
                    mma_bf16(acc[0][nt], aL0, b0h, b1h);
                    mma_bf16(acc[1][nt], aH1, b0h, b1h);
                    mma_bf16(acc[1][nt], aH1, b0l, b1l);
                    mma_bf16(acc[1][nt], aL1, b0h, b1h);
                }
            }
        }
        __syncthreads();
        if (i + 2 < nT) issue(i + 2);
    }

    const size_t hTT = (size_t)h * TT * TT;
#pragma unroll
    for (int mt = 0; mt < 2; mt++) {
#pragma unroll
        for (int nt = 0; nt < 8; nt++) {
#pragma unroll
            for (int half = 0; half < 2; half++) {
                int t = rowBase + wr * 32 + mt * 16 + g + half * 8;
                int j = colBase + wc * 64 + nt * 8 + t4 * 2;
                float v0 = acc[mt][nt][half * 2 + 0];
                float v1 = acc[mt][nt][half * 2 + 1];
                if (mode == 0) {
                    float2 out = {v0, v1};
                    *(float2*)(Cf + hTT + (size_t)t * TT + j) = out;
                } else if (mode == 2) {
                    v0 = (j < t) ? v0 : 0.0f;
                    v1 = (j + 1 < t) ? v1 : 0.0f;
                    float2 out = {v0, v1};
                    *(float2*)(Cf + hTT + (size_t)t * TT + j) = out;
                } else {
                    if (mode == 1) {
                        v0 = (j <= t) ? v0 : 0.0f;
                        v1 = (j + 1 <= t) ? v1 : 0.0f;
                    } else {
                        v0 = (j < t) ? v0 * betaArr[h * TT + j] : 0.0f;
                        v1 = (j + 1 < t) ? v1 * betaArr[h * TT + j + 1] : 0.0f;
                    }
                    unsigned hw, lw;
                    split2pair(v0, v1, hw, lw);
                    *(unsigned*)&CpH[hTT + (size_t)t * TT + j] = hw;
                    *(unsigned*)&CpL[hTT + (size_t)t * TT + j] = lw;
                }
            }
        }
    }
}

// ---------------- in-chunk forward substitution (warp per column, 8 rows/it) -
__global__ __launch_bounds__(256) void chunk_solve(int chunk)
{
    const int h = blockIdx.y;
    const int tid = threadIdx.x, lane = tid & 31, wid = tid >> 5;
    const size_t mo = (size_t)h * TT * TT + (size_t)(chunk * CH) * TT + chunk * CH;
    const size_t bo = (size_t)h * TT * TT + (size_t)(chunk * CH) * TT;
    const int j0 = blockIdx.x * 8;

    __shared__ float Mtri[CH * (CH - 1) / 2];
    __shared__ float bs[CH][9];

    for (int r = wid + 1; r < CH; r += 8) {
        int base = r * (r - 1) / 2;
        for (int s = lane; s < r; s += 32) {
            size_t idx = mo + (size_t)r * TT + s;
            Mtri[base + s] = __bfloat162float(g_Mws[idx]) + __bfloat162float(g_Mws[PLT + idx]);
        }
    }
    {
        int r = tid >> 1, c = (tid & 1) * 4;
        float4 v = *(const float4*)(g_bm + bo + (size_t)r * TT + j0 + c);
        bs[r][c + 0] = v.x; bs[r][c + 1] = v.y; bs[r][c + 2] = v.z; bs[r][c + 3] = v.w;
    }
    __syncthreads();

    // 8 rows per step; 16 serial steps
    for (int r = 0; r < CH; r += 8) {
        int bidx[8];
        float sm[8];
#pragma unroll
        for (int i = 0; i < 8; i++) {
            bidx[i] = (r + i) * (r + i - 1) / 2;
            sm[i] = 0.0f;
        }
        for (int s = lane; s < r; s += 32) {
            float bv = bs[s][wid];
#pragma unroll
            for (int i = 0; i < 8; i++) sm[i] += Mtri[bidx[i] + s] * bv;
        }
#pragma unroll
        for (int o = 16; o > 0; o >>= 1) {
#pragma unroll
            for (int i = 0; i < 8; i++) sm[i] += __shfl_xor_sync(0xffffffffu, sm[i], o);
        }
        if (lane == 0) {
            float v[8];
#pragma unroll
            for (int i = 0; i < 8; i++) {
                float x = bs[r + i][wid] - sm[i];
#pragma unroll
                for (int j = 0; j < 8; j++)
                    if (j < i) x -= Mtri[bidx[i] + r + j] * v[j];
                v[i] = x;
                bs[r + i][wid] = x;
            }
        }
        __syncwarp();
    }
    __syncthreads();

    {
        int r = tid >> 1, c = (tid & 1) * 4;
        float beta = g_beta[h * TT + chunk * CH + r];
        size_t idx = bo + (size_t)r * TT + j0 + c;
        float v0 = bs[r][c], v1 = bs[r][c + 1], v2 = bs[r][c + 2], v3 = bs[r][c + 3];
        unsigned hw, lw;
        split2pair(v0, v1, hw, lw);
        *(unsigned*)&g_bms[idx] = hw; *(unsigned*)&g_bms[PLT + idx] = lw;
        split2pair(v2, v3, hw, lw);
        *(unsigned*)&g_bms[idx + 2] = hw; *(unsigned*)&g_bms[PLT + idx + 2] = lw;
        split2pair(v0 * beta, v1 * beta, hw, lw);
        *(unsigned*)&g_bts[idx] = hw; *(unsigned*)&g_bts[PLT + idx] = lw;
        split2pair(v2 * beta, v3 * beta, hw, lw);
        *(unsigned*)&g_bts[idx + 2] = hw; *(unsigned*)&g_bts[PLT + idx + 2] = lw;
    }
}

// ---------------- fused split of all inputs into bf16 planes -----------------
__global__ void split_all(const float* __restrict__ x,
                          const float* __restrict__ Wq, const float* __restrict__ Wk,
                          const float* __restrict__ Wv, const float* __restrict__ Ww,
                          const float* __restrict__ Wo)
{
    const int b = blockIdx.x;
    if (b < 2048) {
        size_t i = ((size_t)b * 256 + threadIdx.x) * 4;
        float4 v = *(const float4*)(x + i);
        unsigned h01, l01, h23, l23;
        split2pair(v.x, v.y, h01, l01);
        split2pair(v.z, v.w, h23, l23);
        uint2 hh = {h01, h23}, ll = {l01, l23};
        *(uint2*)&g_xs[i] = hh;
        *(uint2*)&g_xs[PLD + i] = ll;
    } else if (b < 6144) {
        const int wsel = (b - 2048) >> 10;
        const float* W = (wsel == 0) ? Wq : (wsel == 1) ? Wk : (wsel == 2) ? Wv : Ww;
        const int colOfs = wsel * 1024;
        int i = ((b - 2048) & 1023) * 256 + threadIdx.x;
        int e = i * 4;
        int r = e >> 10, c = e & 1023;
        float4 v = *(const float4*)(W + (size_t)r * 1024 + c);
        unsigned h01, l01, h23, l23;
        split2pair(v.x, v.y, h01, l01);
        split2pair(v.z, v.w, h23, l23);
        size_t dst = (size_t)r * 4096 + colOfs + c;
        uint2 hh = {h01, h23}, ll = {l01, l23};
        *(uint2*)&g_W4s[dst] = hh;
        *(uint2*)&g_W4s[PLW + dst] = ll;
    } else {
        size_t i = ((size_t)(b - 6144) * 256 + threadIdx.x) * 4;
        float4 v = *(const float4*)(Wo + i);
        unsigned h01, l01, h23, l23;
        split2pair(v.x, v.y, h01, l01);
        split2pair(v.z, v.w, h23, l23);
        uint2 hh = {h01, h23}, ll = {l01, l23};
        *(uint2*)&g_Wos[i] = hh;
        *(uint2*)&g_Wos[PLO + i] = ll;
    }
}

// ---------------- reduce 4 split-K partials into O planes (row-half) ---------
__global__ void reduce_pv(size_t ofs)
{
    size_t i = ofs + ((size_t)blockIdx.x * 256 + threadIdx.x) * 4;
    float4 a = *(const float4*)(g_raw + i);
    float4 b = *(const float4*)(g_raw + i + PLD);
    float4 c = *(const float4*)(g_raw + i + 2 * PLD);
    float4 d = *(const float4*)(g_raw + i + 3 * PLD);
    float4 o = {a.x + b.x + c.x + d.x, a.y + b.y + c.y + d.y,
                a.z + b.z + c.z + d.z, a.w + b.w + c.w + d.w};
    unsigned h01, l01, h23, l23;
    split2pair(o.x, o.y, h01, l01);
    split2pair(o.z, o.w, h23, l23);
    uint2 hh = {h01, h23}, ll = {l01, l23};
    *(uint2*)&g_Os[i] = hh;
    *(uint2*)&g_Os[PLD + i] = ll;
}

// ---------------- prep: rms(q,k), v, conv+silu+l2norm w -> bf16 planes -------
__device__ __forceinline__ float block_reduce_64(float v, float* sh)
{
    int tid = threadIdx.x;
    sh[tid] = v; __syncthreads();
    for (int s = 32; s > 0; s >>= 1) {
        if (tid < s) sh[tid] += sh[tid + s];
        __syncthreads();
    }
    float r = sh[0]; __syncthreads();
    return r;
}

__global__ void prep_kernel(const float* __restrict__ qn_w,
                            const float* __restrict__ kn_w,
                            const float* __restrict__ convw)
{
    const int t = blockIdx.x, h = blockIdx.y;
    const int c0 = threadIdx.x * 2;
    __shared__ float sh[64];
    const int col = h * HD + c0;
    const size_t rowb = (size_t)t * 4096;
    const size_t out = ((size_t)h * TT + t) * HD + c0;
    unsigned hw, lw;

    float q0 = g_raw[rowb + col], q1 = g_raw[rowb + col + 1];
    float s = block_reduce_64(q0 * q0 + q1 * q1, sh);
    float rq = rsqrtf(s * (1.0f / HD) + 1e-6f);
    split2pair(q0 * rq * qn_w[c0], q1 * rq * qn_w[c0 + 1], hw, lw);
    *(unsigned*)&g_qs[out] = hw; *(unsigned*)&g_qs[PLQ + out] = lw;

    float k0 = g_raw[rowb + 1024 + col], k1 = g_raw[rowb + 1024 + col + 1];
    s = block_reduce_64(k0 * k0 + k1 * k1, sh);
    float rk = rsqrtf(s * (1.0f / HD) + 1e-6f);
    split2pair(k0 * rk * kn_w[c0], k1 * rk * kn_w[c0 + 1], hw, lw);
    *(unsigned*)&g_ks[out] = hw; *(unsigned*)&g_ks[PLQ + out] = lw;

    split2pair(g_raw[rowb + 2048 + col], g_raw[rowb + 2048 + col + 1], hw, lw);
    *(unsigned*)&g_vs[out] = hw; *(unsigned*)&g_vs[PLQ + out] = lw;

    float w0 = 0.0f, w1 = 0.0f;
#pragma unroll
    for (int tap = 0; tap < KC; tap++) {
        int tt = t - (KC - 1) + tap;
        if (tt >= 0) {
            w0 += g_raw[(size_t)tt * 4096 + 3072 + col] * convw[col * KC + tap];
            w1 += g_raw[(size_t)tt * 4096 + 3072 + col + 1] * convw[(col + 1) * KC + tap];
        }
    }
    w0 = w0 / (1.0f + __expf(-w0));
    w1 = w1 / (1.0f + __expf(-w1));
    s = block_reduce_64(w0 * w0 + w1 * w1, sh);
    float rw = rsqrtf(s + 1e-6f);
    split2pair(w0 * rw, w1 * rw, hw, lw);
    *(unsigned*)&g_ws2[out] = hw; *(unsigned*)&g_ws2[PLQ + out] = lw;
}

// ---------------- beta = 2*sigmoid(x@Wbeta), gpre = x@Wg --------------------
__global__ void betag_kernel(const float* __restrict__ x,
                             const float* __restrict__ Wbeta,
                             const float* __restrict__ Wg)
{
    const int t = blockIdx.x;
    const int tid = threadIdx.x;
    const int wid = tid >> 5, lane = tid & 31;
    const float* xr = x + (size_t)t * DD;
    float sb = 0.0f, sg = 0.0f;
    for (int dd = lane; dd < DD; dd += 32) {
        float xv = xr[dd];
        sb += xv * Wbeta[dd * NH + wid];
        sg += xv * Wg[dd * NH + wid];
    }
#pragma unroll
    for (int o = 16; o > 0; o >>= 1) {
        sb += __shfl_down_sync(0xffffffffu, sb, o);
        sg += __shfl_down_sync(0xffffffffu, sg, o);
    }
    if (lane == 0) {
        g_beta[wid * TT + t] = 2.0f / (1.0f + __expf(-sb));
        g_gpre[wid * TT + t] = sg;
    }
}

// ---------------- G = cumsum(log_sigmoid) -- parallel block scan per head ----
__global__ void cumsum_kernel()     // grid = NH, 512 threads, 4 elems/thread
{
    const int h = blockIdx.x;
    const int tid = threadIdx.x, lane = tid & 31, wrp = tid >> 5;
    __shared__ float wsum[16];
    float v[4];
    float run = 0.0f;
#pragma unroll
    for (int u = 0; u < 4; u++) {
        float x = g_gpre[h * TT + tid * 4 + u];
        float ls = fminf(x, 0.0f) - log1pf(__expf(-fabsf(x)));
        run += ls;
        v[u] = run;
    }
    const float tmine = run;
    float tot = run;
#pragma unroll
    for (int o = 1; o < 32; o <<= 1) {
        float t = __shfl_up_sync(0xffffffffu, tot, o);
        if (lane >= o) tot += t;
    }
    if (lane == 31) wsum[wrp] = tot;
    __syncthreads();
    if (wrp == 0) {
        float w = (lane < 16) ? wsum[lane] : 0.0f;
#pragma unroll
        for (int o = 1; o < 16; o <<= 1) {
            float t = __shfl_up_sync(0xffffffffu, w, o);
            if (lane >= o) w += t;
        }
        if (lane < 16) wsum[lane] = w;
    }
    __syncthreads();
    float off = (tot - tmine) + (wrp > 0 ? wsum[wrp - 1] : 0.0f);
#pragma unroll
    for (int u = 0; u < 4; u++)
        g_G[h * TT + tid * 4 + u] = v[u] + off;
}

// ---------------- masked softmax; row-half via rowOfs ------------------------
__global__ void softmax_kernel(int rowOfs)
{
    const int t = blockIdx.x + rowOfs, h = blockIdx.y;
    const size_t ro = ((size_t)h * TT + t) * TT;
    const float* row = g_A + ro;
    const float* Gh = g_G + h * TT;
    const float Gt = Gh[t];
    const int n = t + 1;
    const int tid = threadIdx.x;
    __shared__ float buf[TT];
    __shared__ float red[256];

    float m = -1e30f;
    for (int j = tid; j < n; j += 256) {
        float l = row[j] * ATT_SCALE + Gt - Gh[j];
        buf[j] = l;
        m = fmaxf(m, l);
    }
    red[tid] = m; __syncthreads();
    for (int s = 128; s > 0; s >>= 1) {
        if (tid < s) red[tid] = fmaxf(red[tid], red[tid + s]);
        __syncthreads();
    }
    m = red[0]; __syncthreads();

    float sum = 0.0f;
    for (int j = tid; j < n; j += 256) sum += __expf(buf[j] - m);
    red[tid] = sum; __syncthreads();
    for (int s = 128; s > 0; s >>= 1) {
        if (tid < s) red[tid] += red[tid + s];
        __syncthreads();
    }
    const float inv = 1.0f / red[0];

    for (int jj = tid; jj < TT / 2; jj += 256) {
        int j0 = jj * 2;
        float p0 = (j0 < n) ? __expf(buf[j0] - m) * inv : 0.0f;
        float p1 = (j0 + 1 < n) ? __expf(buf[j0 + 1] - m) * inv : 0.0f;
        unsigned hw, lw;
        split2pair(p0, p1, hw, lw);
        *(unsigned*)&g_Ps[ro + j0] = hw;
        *(unsigned*)&g_Ps[PLT + ro + j0] = lw;
    }
}

// ---------------------------------------------------------------------------
extern "C" void kernel_launch(void* const* d_in, const int* in_sizes, int n_in,
                              void* d_out, int out_size)
{
    const float* x     = (const float*)d_in[0];
    const float* Wq    = (const float*)d_in[1];
    const float* Wk    = (const float*)d_in[2];
    const float* Wv    = (const float*)d_in[3];
    const float* Ww    = (const float*)d_in[4];
    const float* Wbeta = (const float*)d_in[5];
    const float* Wg    = (const float*)d_in[6];
    const float* Wo    = (const float*)d_in[7];
    const float* convw = (const float*)d_in[8];
    const float* qnw   = (const float*)d_in[9];
    const float* knw   = (const float*)d_in[10];
    float* out = (float*)d_out;

    cudaFuncSetAttribute(mma_nn_b, cudaFuncAttributeMaxDynamicSharedMemorySize, SMNN);
    cudaFuncSetAttribute(mma_nt_b, cudaFuncAttributeMaxDynamicSharedMemorySize, SMNT);

    static cudaStream_t s2 = nullptr, s3 = nullptr;
    static cudaEvent_t evF0 = nullptr, evS0 = nullptr, evF1 = nullptr, evS1 = nullptr;
    static cudaEvent_t evTL = nullptr, evOutL = nullptr;
    static cudaEvent_t evSol[NCHUNK] = {};
    static cudaEvent_t evRest[NCHUNK] = {};
    if (!s2) {
        cudaStreamCreateWithFlags(&s2, cudaStreamNonBlocking);
        cudaStreamCreateWithFlags(&s3, cudaStreamNonBlocking);
        cudaEventCreateWithFlags(&evF0, cudaEventDisableTiming);
        cudaEventCreateWithFlags(&evS0, cudaEventDisableTiming);
        cudaEventCreateWithFlags(&evF1, cudaEventDisableTiming);
        cudaEventCreateWithFlags(&evS1, cudaEventDisableTiming);
        cudaEventCreateWithFlags(&evTL, cudaEventDisableTiming);
        cudaEventCreateWithFlags(&evOutL, cudaEventDisableTiming);
        for (int i = 0; i < NCHUNK; i++) {
            cudaEventCreateWithFlags(&evSol[i], cudaEventDisableTiming);
            cudaEventCreateWithFlags(&evRest[i], cudaEventDisableTiming);
        }
    }

    float *raw, *A, *bm, *beta;
    __nv_bfloat16 *xs, *W4s, *Wos, *qs, *ks, *vs, *ws, *QWs, *Mws, *Ps, *bms, *bts, *Os;
    cudaGetSymbolAddress((void**)&raw, g_raw);
    cudaGetSymbolAddress((void**)&A, g_A);
    cudaGetSymbolAddress((void**)&bm, g_bm);
    cudaGetSymbolAddress((void**)&beta, g_beta);
    cudaGetSymbolAddress((void**)&xs, g_xs);
    cudaGetSymbolAddress((void**)&W4s, g_W4s);
    cudaGetSymbolAddress((void**)&Wos, g_Wos);
    cudaGetSymbolAddress((void**)&qs, g_qs);
    cudaGetSymbolAddress((void**)&ks, g_ks);
    cudaGetSymbolAddress((void**)&vs, g_vs);
    cudaGetSymbolAddress((void**)&ws, g_ws2);
    cudaGetSymbolAddress((void**)&QWs, g_QWs);
    cudaGetSymbolAddress((void**)&Mws, g_Mws);
    cudaGetSymbolAddress((void**)&Ps, g_Ps);
    cudaGetSymbolAddress((void**)&bms, g_bms);
    cudaGetSymbolAddress((void**)&bts, g_bts);
    cudaGetSymbolAddress((void**)&Os, g_Os);

    const long long TTTT = (long long)TT * TT;

    // fork A: betag+cumsum on side stream, overlapping split+proj on main
    cudaEventRecord(evF0, 0);
    cudaStreamWaitEvent(s2, evF0, 0);
    betag_kernel<<<TT, 256, 0, s2>>>(x, Wbeta, Wg);
    cumsum_kernel<<<NH, 512, 0, s2>>>();
    cudaEventRecord(evS0, s2);

    split_all<<<7168, 256>>>(x, Wq, Wk, Wv, Ww, Wo);
    mma_nn_b<<<dim3(4 * DD / BN, TT / BM, 1), 256, SMNN>>>(
        xs, xs + PLD, W4s, W4s + PLW, raw, DD, DD, 4 * DD, 4 * DD, 0, 0, 0, 0, 0);
    prep_kernel<<<dim3(TT, NH), 64>>>(qnw, knw, convw);
    cudaStreamWaitEvent(0, evS0, 0);      // beta/G ready

    const dim3 gNT(TT / BN, TT / BM, NH);
    // solve-chain inputs first
    mma_nt_b<<<gNT, 256, SMNT>>>(ws, ws + PLQ, ks, ks + PLQ, bm, nullptr, nullptr, nullptr, 2);   // rhs
    mma_nt_b<<<gNT, 256, SMNT>>>(ws, ws + PLQ, ws, ws + PLQ, nullptr, Mws, Mws + PLT, beta, 3);   // Mw

    // fork B: lookahead solve chain — s2 = critical (narrow update + solve),
    // s3 = off-critical rest-of-trailing updates.
    cudaEventRecord(evF1, 0);
    cudaStreamWaitEvent(s2, evF1, 0);
    cudaStreamWaitEvent(s3, evF1, 0);
    chunk_solve<<<dim3(16, NH), 256, 0, s2>>>(0);
    cudaEventRecord(evSol[0], s2);
    for (int c = 0; c < NCHUNK - 1; c++) {
        size_t moN = (size_t)(c + 1) * CH * TT + (size_t)c * CH;
        size_t bo  = (size_t)c * CH * TT;
        if (c >= 1) cudaStreamWaitEvent(s2, evRest[c - 1], 0);
        mma_nn_b<<<dim3(c + 1, 1, NH), 256, SMNN, s2>>>(
            Mws + moN, Mws + PLT + moN, bms + bo, bms + PLT + bo,
            bm + (size_t)(c + 1) * CH * TT,
            CH, TT, TT, TT, TTTT, TTTT, TTTT, 1, 0);
        chunk_solve<<<dim3((c + 2) * 16, NH), 256, 0, s2>>>(c + 1);
        cudaEventRecord(evSol[c + 1], s2);
        if (c < NCHUNK - 2) {
            size_t moR = (size_t)(c + 2) * CH * TT + (size_t)c * CH;
            cudaStreamWaitEvent(s3, evSol[c], 0);
            mma_nn_b<<<dim3(c + 1, NCHUNK - 2 - c, NH), 256, SMNN, s3>>>(
                Mws + moR, Mws + PLT + moR, bms + bo, bms + PLT + bo,
                bm + (size_t)(c + 2) * CH * TT,
                CH, TT, TT, TT, TTTT, TTTT, TTTT, 1, 0);
            cudaEventRecord(evRest[c], s3);
        }
    }
    cudaEventRecord(evS1, s2);

    // main stream: QK^T and tril(QW^T) overlap the chain
    mma_nt_b<<<gNT, 256, SMNT>>>(qs, qs + PLQ, ks, ks + PLQ, A, nullptr, nullptr, nullptr, 0);     // QK^T
    mma_nt_b<<<gNT, 256, SMNT>>>(qs, qs + PLQ, ws, ws + PLQ, nullptr, QWs, QWs + PLT, nullptr, 1); // tril(QW)
    cudaStreamWaitEvent(0, evS1, 0);      // join: btil ready

    // ---- row-half pipelined epilogue ----
    mma_nn_b<<<dim3(8, 8, NH), 256, SMNN>>>(QWs, QWs + PLT, bts, bts + PLT, A,
                                            TT, TT, TT, TT, TTTT, TTTT, TTTT, 3, 0);
    cudaEventRecord(evTL, 0);
    mma_nn_b<<<dim3(16, 8, NH), 256, SMNN>>>(QWs, QWs + PLT, bts, bts + PLT, A,
                                             TT, TT, TT, TT, TTTT, TTTT, TTTT, 3, 8);

    cudaStreamWaitEvent(s3, evTL, 0);
    softmax_kernel<<<dim3(1024, NH), 256, 0, s3>>>(0);
    mma_nn_b<<<dim3(1, 8, NH * 4), 256, SMNN, s3>>>(
        Ps, Ps + PLT, vs, vs + PLQ, raw, TT, TT, HD, DD,
        TTTT, (long long)TT * HD, HD, 8, 0);
    reduce_pv<<<1024, 256, 0, s3>>>(0);
    mma_nn_b<<<dim3(DD / BN, 8, 1), 256, SMNN, s3>>>(
        Os, Os + PLD, Wos, Wos + PLO, out, DD, DD, DD, DD, 0, 0, 0, 0, 0);
    cudaEventRecord(evOutL, s3);

    softmax_kernel<<<dim3(1024, NH), 256>>>(1024);
    mma_nn_b<<<dim3(1, 8, NH * 4), 256, SMNN>>>(
        Ps, Ps + PLT, vs, vs + PLQ, raw, TT, TT, HD, DD,
        TTTT, (long long)TT * HD, HD, 8, 8);
    reduce_pv<<<1024, 256>>>((size_t)1024 * DD);
    mma_nn_b<<<dim3(DD / BN, 8, 1), 256, SMNN>>>(
        Os, Os + PLD, Wos, Wos + PLO, out, DD, DD, DD, DD, 0, 0, 0, 0, 8);

    cudaStreamWaitEvent(0, evOutL, 0);    // join lower-half pipeline
}

// round 17
// speedup vs baseline: 1.0346x; 1.0346x over previous
#include <cuda_runtime.h>
#include <cuda_bf16.h>
#include <math.h>

#define TT 2048
#define DD 1024
#define NH 8
#define HD 128
#define KC 4
#define CH 128
#define NCHUNK (TT / CH)
#define BM 128
#define BN 128
#define BKK 32
#define ATT_SCALE 0.08838834764831845f  // 1/sqrt(128)

#define PLD ((size_t)TT * DD)
#define PLQ ((size_t)NH * TT * HD)
#define PLT ((size_t)NH * TT * TT)
#define PLW ((size_t)DD * 4 * DD)
#define PLO ((size_t)DD * DD)

// smem stage layout (bytes)
#define NN_AH 0
#define NN_AL 10240
#define NN_BH 20480
#define NN_BL 29184
#define NN_STAGE_B 37888
#define SMNN (3 * NN_STAGE_B)          // 3-stage pipeline
#define NT_AH 0
#define NT_AL 10240
#define NT_BH 20480
#define NT_BL 30720
#define NT_STAGE_B 40960
#define SMNT (2 * NT_STAGE_B)

// ---------------- scratch (device globals) ----------------------------------
__device__ float g_raw[(size_t)TT * 4 * DD];   // projections; later PV partials
__device__ __nv_bfloat16 g_xs[2 * PLD];
__device__ __nv_bfloat16 g_W4s[2 * PLW];
__device__ __nv_bfloat16 g_Wos[2 * PLO];
__device__ __nv_bfloat16 g_qs[2 * PLQ];
__device__ __nv_bfloat16 g_ks[2 * PLQ];
__device__ __nv_bfloat16 g_vs[2 * PLQ];
__device__ __nv_bfloat16 g_ws2[2 * PLQ];
__device__ __nv_bfloat16 g_QWs[2 * PLT];
__device__ __nv_bfloat16 g_Mws[2 * PLT];
__device__ __nv_bfloat16 g_Ps[2 * PLT];
__device__ __nv_bfloat16 g_bms[2 * PLT];
__device__ __nv_bfloat16 g_bts[2 * PLT];
__device__ __nv_bfloat16 g_Os[2 * PLD];
__device__ float g_A[PLT];
__device__ float g_bm[PLT];
__device__ float g_beta[NH * TT];
__device__ float g_gpre[NH * TT];
__device__ float g_G[NH * TT];

// ---------------- helpers ----------------------------------------------------
__device__ __forceinline__ unsigned smem_u32(const void* p) {
    return (unsigned)__cvta_generic_to_shared(p);
}
__device__ __forceinline__ void ldm_x4(unsigned addr, unsigned* r) {
    asm volatile("ldmatrix.sync.aligned.m8n8.x4.shared.b16 {%0,%1,%2,%3}, [%4];"
        : "=r"(r[0]), "=r"(r[1]), "=r"(r[2]), "=r"(r[3]) : "r"(addr));
}
__device__ __forceinline__ void ldm_x4t(unsigned addr, unsigned* r) {
    asm volatile("ldmatrix.sync.aligned.m8n8.x4.trans.shared.b16 {%0,%1,%2,%3}, [%4];"
        : "=r"(r[0]), "=r"(r[1]), "=r"(r[2]), "=r"(r[3]) : "r"(addr));
}
__device__ __forceinline__ void mma_bf16(float* c, const unsigned* a, unsigned b0, unsigned b1) {
    asm volatile(
        "mma.sync.aligned.m16n8k16.row.col.f32.bf16.bf16.f32 "
        "{%0,%1,%2,%3}, {%4,%5,%6,%7}, {%8,%9}, {%0,%1,%2,%3};"
        : "+f"(c[0]), "+f"(c[1]), "+f"(c[2]), "+f"(c[3])
        : "r"(a[0]), "r"(a[1]), "r"(a[2]), "r"(a[3]), "r"(b0), "r"(b1));
}
__device__ __forceinline__ void cp16(unsigned dst, const void* src) {
    asm volatile("cp.async.cg.shared.global [%0], [%1], 16;" :: "r"(dst), "l"(src));
}
#define CP_COMMIT() asm volatile("cp.async.commit_group;" ::: "memory")
__device__ __forceinline__ void cp_wait0() { asm volatile("cp.async.wait_group 0;" ::: "memory"); }
__device__ __forceinline__ void cp_wait1() { asm volatile("cp.async.wait_group 1;" ::: "memory"); }

// pack two floats into bf16x2 hi + lo planes
__device__ __forceinline__ void split2pair(float a, float b, unsigned& h, unsigned& l) {
    __nv_bfloat16 ha = __float2bfloat16(a), hb = __float2bfloat16(b);
    float ra = a - __bfloat162float(ha), rb = b - __bfloat162float(hb);
    __nv_bfloat162 H(ha, hb);
    __nv_bfloat162 L(__float2bfloat16(ra), __float2bfloat16(rb));
    h = *reinterpret_cast<unsigned*>(&H);
    l = *reinterpret_cast<unsigned*>(&L);
}

// ---------------- NN GEMM on bf16 hi/lo planes, 3-stage cp.async ------------
// flags: 1 = subtract; 2 = triangular; 4 = causal K; 8 = split-K PV.
// yOfs shifts the row-tile index (row-half pipelining). Triangular mode
// processes y in descending order (long-K tiles first).
__global__ __launch_bounds__(256, 2) void mma_nn_b(
    const __nv_bfloat16* __restrict__ AH, const __nv_bfloat16* __restrict__ AL,
    const __nv_bfloat16* __restrict__ BH, const __nv_bfloat16* __restrict__ BL,
    float* __restrict__ C,
    int K, int lda, int ldb, int ldc,
    long long sA, long long sB, long long sC, int flags, int yOfs)
{
    const int bx = blockIdx.x;
    int by;
    if (flags & 2) {
        by = yOfs + (gridDim.y - 1 - blockIdx.y);   // descending
        if (bx > by) return;
    } else {
        by = yOfs + blockIdx.y;
    }
    const int rowBase = by * BM, colBase = bx * BN;
    int kBeg, kEnd;
    if (flags & 8) {
        int h = blockIdx.z & 7, sp = blockIdx.z >> 3;
        AH += (long long)h * sA; AL += (long long)h * sA;
        BH += (long long)h * sB; BL += (long long)h * sB;
        C += (size_t)sp * TT * DD + (long long)h * sC;
        kBeg = sp * 512;
        kEnd = min(min(K, rowBase + BM), kBeg + 512);
    } else {
        AH += (long long)blockIdx.z * sA; AL += (long long)blockIdx.z * sA;
        BH += (long long)blockIdx.z * sB; BL += (long long)blockIdx.z * sB;
        C += (long long)blockIdx.z * sC;
        kBeg = (flags & 2) ? colBase : 0;
        kEnd = (flags & 6) ? min(K, rowBase + BM) : K;
    }
    const int nT = (kEnd > kBeg) ? (kEnd - kBeg) / BKK : 0;
    if (nT <= 0 && (flags & 1)) return;

    extern __shared__ __align__(16) char smch[];
    const unsigned smb = smem_u32(smch);

    const int tid = threadIdx.x, lane = tid & 31, wid = tid >> 5;
    const int wr = wid & 3, wc = wid >> 2;
    const int g = lane >> 2, t4 = lane & 3;
    const int ar = tid >> 2, aq = (tid & 3) * 8;
    const int br = tid >> 4, bq = (tid & 15) * 8;

    float acc[2][8][4] = {};

    auto issue = [&](int it) {
        const int kk = kBeg + it * BKK;
        const unsigned st = smb + (it % 3) * NN_STAGE_B;
        cp16(st + NN_AH + ar * 80 + aq * 2, AH + (size_t)(rowBase + ar) * lda + kk + aq);
        cp16(st + NN_AH + (ar + 64) * 80 + aq * 2, AH + (size_t)(rowBase + ar + 64) * lda + kk + aq);
        cp16(st + NN_AL + ar * 80 + aq * 2, AL + (size_t)(rowBase + ar) * lda + kk + aq);
        cp16(st + NN_AL + (ar + 64) * 80 + aq * 2, AL + (size_t)(rowBase + ar + 64) * lda + kk + aq);
        cp16(st + NN_BH + br * 272 + bq * 2, BH + (size_t)(kk + br) * ldb + colBase + bq);
        cp16(st + NN_BH + (br + 16) * 272 + bq * 2, BH + (size_t)(kk + br + 16) * ldb + colBase + bq);
        cp16(st + NN_BL + br * 272 + bq * 2, BL + (size_t)(kk + br) * ldb + colBase + bq);
        cp16(st + NN_BL + (br + 16) * 272 + bq * 2, BL + (size_t)(kk + br + 16) * ldb + colBase + bq);
        CP_COMMIT();
    };

    if (nT > 0) issue(0);
    if (nT > 1) issue(1);

    for (int i = 0; i < nT; i++) {
        if (i + 1 < nT) cp_wait1(); else cp_wait0();
        __syncthreads();
        if (i + 2 < nT) issue(i + 2);
        const unsigned st = smb + (i % 3) * NN_STAGE_B;
#pragma unroll
        for (int k16 = 0; k16 < BKK; k16 += 16) {
            unsigned aH0[4], aH1[4], aL0[4], aL1[4];
            const int rA = wr * 32 + (lane & 7) + ((lane >> 3) & 1) * 8;
            const int cA = k16 + (lane >> 4) * 8;
            ldm_x4(st + NN_AH + rA * 80 + cA * 2, aH0);
            ldm_x4(st + NN_AH + (rA + 16) * 80 + cA * 2, aH1);
            ldm_x4(st + NN_AL + rA * 80 + cA * 2, aL0);
            ldm_x4(st + NN_AL + (rA + 16) * 80 + cA * 2, aL1);
            const int rB = k16 + (lane & 7) + ((lane >> 3) & 1) * 8;
            const int cB = wc * 64 + (lane >> 4) * 8;
#pragma unroll
            for (int nq = 0; nq < 4; nq++) {
                unsigned bH[4], bL[4];
                ldm_x4t(st + NN_BH + rB * 272 + (cB + nq * 16) * 2, bH);
                ldm_x4t(st + NN_BL + rB * 272 + (cB + nq * 16) * 2, bL);
#pragma unroll
                for (int sub = 0; sub < 2; sub++) {
                    const int nt = nq * 2 + sub;
                    unsigned b0h = bH[sub * 2], b1h = bH[sub * 2 + 1];
                    unsigned b0l = bL[sub * 2], b1l = bL[sub * 2 + 1];
                    mma_bf16(acc[0][nt], aH0, b0h, b1h);
                    mma_bf16(acc[0][nt], aH0, b0l, b1l);
                    mma_bf16(acc[0][nt], aL0, b0h, b1h);
                    mma_bf16(acc[1][nt], aH1, b0h, b1h);
                    mma_bf16(acc[1][nt], aH1, b0l, b1l);
                    mma_bf16(acc[1][nt], aL1, b0h, b1h);
                }
            }
        }
    }

#pragma unroll
    for (int mt = 0; mt < 2; mt++) {
#pragma unroll
        for (int nt = 0; nt < 8; nt++) {
            int r0 = rowBase + wr * 32 + mt * 16 + g;
            int c0 = colBase + wc * 64 + nt * 8 + t4 * 2;
            float* p0 = C + (long long)r0 * ldc + c0;
            float* p1 = C + (long long)(r0 + 8) * ldc + c0;
            if (flags & 1) {
                float2 v0 = *(float2*)p0;
                v0.x -= acc[mt][nt][0]; v0.y -= acc[mt][nt][1];
                *(float2*)p0 = v0;
                float2 v1 = *(float2*)p1;
                v1.x -= acc[mt][nt][2]; v1.y -= acc[mt][nt][3];
                *(float2*)p1 = v1;
            } else {
                float2 v0 = {acc[mt][nt][0], acc[mt][nt][1]};
                float2 v1 = {acc[mt][nt][2], acc[mt][nt][3]};
                *(float2*)p0 = v0;
                *(float2*)p1 = v1;
            }
        }
    }
}

// ---------------- NT GEMM (A @ B^T) on bf16 planes, [T,128] heads -----------
// modes: 0 = QK^T -> f32; 1 = tril(QW^T,0) -> planes; 2 = strict lower -> f32
// (upper tiles zero-filled); 3 = strict-lower * beta[col] -> planes.
__global__ __launch_bounds__(256, 2) void mma_nt_b(
    const __nv_bfloat16* __restrict__ AH, const __nv_bfloat16* __restrict__ AL,
    const __nv_bfloat16* __restrict__ BH, const __nv_bfloat16* __restrict__ BL,
    float* __restrict__ Cf, __nv_bfloat16* __restrict__ CpH, __nv_bfloat16* __restrict__ CpL,
    const float* __restrict__ betaArr, int mode)
{
    const int bx = blockIdx.x, by = blockIdx.y, h = blockIdx.z;
    const int rowBase = by * BM, colBase = bx * BN;
    const int tid = threadIdx.x, lane = tid & 31, wid = tid >> 5;
    if (bx > by) {
        if (mode == 2) {
            float* Ch = Cf + (size_t)h * TT * TT;
            float4 z = {0.f, 0.f, 0.f, 0.f};
#pragma unroll
            for (int i = 0; i < 16; i++) {
                int fid = i * 256 + tid;
                int r = fid >> 5, c = (fid & 31) * 4;
                *(float4*)(Ch + (size_t)(rowBase + r) * TT + colBase + c) = z;
            }
        }
        return;
    }
    const size_t hq = (size_t)h * TT * HD;
    AH += hq; AL += hq; BH += hq; BL += hq;

    extern __shared__ __align__(16) char smch[];
    const unsigned smb = smem_u32(smch);

    const int wr = wid & 3, wc = wid >> 2;
    const int g = lane >> 2, t4 = lane & 3;
    const int ar = tid >> 2, aq = (tid & 3) * 8;

    float acc[2][8][4] = {};

    auto issue = [&](int it) {
        const int kk = it * BKK;
        const unsigned st = smb + (it & 1) * NT_STAGE_B;
        cp16(st + NT_AH + ar * 80 + aq * 2, AH + (size_t)(rowBase + ar) * HD + kk + aq);
        cp16(st + NT_AH + (ar + 64) * 80 + aq * 2, AH + (size_t)(rowBase + ar + 64) * HD + kk + aq);
        cp16(st + NT_AL + ar * 80 + aq * 2, AL + (size_t)(rowBase + ar) * HD + kk + aq);
        cp16(st + NT_AL + (ar + 64) * 80 + aq * 2, AL + (size_t)(rowBase + ar + 64) * HD + kk + aq);
        cp16(st + NT_BH + ar * 80 + aq * 2, BH + (size_t)(colBase + ar) * HD + kk + aq);
        cp16(st + NT_BH + (ar + 64) * 80 + aq * 2, BH + (size_t)(colBase + ar + 64) * HD + kk + aq);
        cp16(st + NT_BL + ar * 80 + aq * 2, BL + (size_t)(colBase + ar) * HD + kk + aq);
        cp16(st + NT_BL + (ar + 64) * 80 + aq * 2, BL + (size_t)(colBase + ar + 64) * HD + kk + aq);
        CP_COMMIT();
    };

    const int nT = HD / BKK;   // 4
    issue(0);
    issue(1);

    for (int i = 0; i < nT; i++) {
        if (i + 1 < nT) cp_wait1(); else cp_wait0();
        __syncthreads();
        const unsigned st = smb + (i & 1) * NT_STAGE_B;
#pragma unroll
        for (int k16 = 0; k16 < BKK; k16 += 16) {
            unsigned aH0[4], aH1[4], aL0[4], aL1[4];
            const int rA = wr * 32 + (lane & 7) + ((lane >> 3) & 1) * 8;
            const int cA = k16 + (lane >> 4) * 8;
            ldm_x4(st + NT_AH + rA * 80 + cA * 2, aH0);
            ldm_x4(st + NT_AH + (rA + 16) * 80 + cA * 2, aH1);
            ldm_x4(st + NT_AL + rA * 80 + cA * 2, aL0);
            ldm_x4(st + NT_AL + (rA + 16) * 80 + cA * 2, aL1);
            const int rBn = wc * 64 + ((lane >> 4) & 1) * 8 + (lane & 7);
            const int cBn = k16 + ((lane >> 3) & 1) * 8;
#pragma unroll
            for (int nq = 0; nq < 4; nq++) {
                unsigned bH[4], bL[4];
                ldm_x4(st + NT_BH + (rBn + nq * 16) * 80 + cBn * 2, bH);
                ldm_x4(st + NT_BL + (rBn + nq * 16) * 80 + cBn * 2, bL);
#pragma unroll
                for (int sub = 0; sub < 2; sub++) {
                    const int nt = nq * 2 + sub;
                    unsigned b0h = bH[sub * 2], b1h = bH[sub * 2 + 1];
                    unsigned b0l = bL[sub * 2], b1l = bL[sub * 2 + 1];
                    mma_bf16(acc[0][nt], aH0, b0h, b1h);
                    mma_bf16(acc[0][nt], aH0, b0l, b1l);
                    mma_bf16(acc[0][nt], aL0, b0h, b1h);
                    mma_bf16(acc[1][nt], aH1, b0h, b1h);
                    mma_bf16(acc[1][nt], aH1, b0l, b1l);
                    mma_bf16(acc[1][nt], aL1, b0h, b1h);
                }
            }
        }
        __syncthreads();
        if (i + 2 < nT) issue(i + 2);
    }

    const size_t hTT = (size_t)h * TT * TT;
#pragma unroll
    for (int mt = 0; mt < 2; mt++) {
#pragma unroll
        for (int nt = 0; nt < 8; nt++) {
#pragma unroll
            for (int half = 0; half < 2; half++) {
                int t = rowBase + wr * 32 + mt * 16 + g + half * 8;
                int j = colBase + wc * 64 + nt * 8 + t4 * 2;
                float v0 = acc[mt][nt][half * 2 + 0];
                float v1 = acc[mt][nt][half * 2 + 1];
                if (mode == 0) {
                    float2 out = {v0, v1};
                    *(float2*)(Cf + hTT + (size_t)t * TT + j) = out;
                } else if (mode == 2) {
                    v0 = (j < t) ? v0 : 0.0f;
                    v1 = (j + 1 < t) ? v1 : 0.0f;
                    float2 out = {v0, v1};
                    *(float2*)(Cf + hTT + (size_t)t * TT + j) = out;
                } else {
                    if (mode == 1) {
                        v0 = (j <= t) ? v0 : 0.0f;
                        v1 = (j + 1 <= t) ? v1 : 0.0f;
                    } else {
                        v0 = (j < t) ? v0 * betaArr[h * TT + j] : 0.0f;
                        v1 = (j + 1 < t) ? v1 * betaArr[h * TT + j + 1] : 0.0f;
                    }
                    unsigned hw, lw;
                    split2pair(v0, v1, hw, lw);
                    *(unsigned*)&CpH[hTT + (size_t)t * TT + j] = hw;
                    *(unsigned*)&CpL[hTT + (size_t)t * TT + j] = lw;
                }
            }
        }
    }
}

// ---------------- in-chunk forward substitution (warp per column, 4 rows/it) -
__global__ __launch_bounds__(256) void chunk_solve(int chunk)
{
    const int h = blockIdx.y;
    const int tid = threadIdx.x, lane = tid & 31, wid = tid >> 5;
    const size_t mo = (size_t)h * TT * TT + (size_t)(chunk * CH) * TT + chunk * CH;
    const size_t bo = (size_t)h * TT * TT + (size_t)(chunk * CH) * TT;
    const int j0 = blockIdx.x * 8;

    __shared__ float Mtri[CH * (CH - 1) / 2];
    __shared__ float bs[CH][9];

    for (int r = wid + 1; r < CH; r += 8) {
        int base = r * (r - 1) / 2;
        for (int s = lane; s < r; s += 32) {
            size_t idx = mo + (size_t)r * TT + s;
            Mtri[base + s] = __bfloat162float(g_Mws[idx]) + __bfloat162float(g_Mws[PLT + idx]);
        }
    }
    {
        int r = tid >> 1, c = (tid & 1) * 4;
        float4 v = *(const float4*)(g_bm + bo + (size_t)r * TT + j0 + c);
        bs[r][c + 0] = v.x; bs[r][c + 1] = v.y; bs[r][c + 2] = v.z; bs[r][c + 3] = v.w;
    }
    __syncthreads();

    // 4 rows per step; 32 serial steps
    for (int r = 0; r < CH; r += 4) {
        const int b0 = r * (r - 1) / 2;
        const int b1 = (r + 1) * r / 2;
        const int b2 = (r + 2) * (r + 1) / 2;
        const int b3 = (r + 3) * (r + 2) / 2;
        float s0 = 0.f, s1 = 0.f, s2 = 0.f, s3 = 0.f;
        for (int s = lane; s < r; s += 32) {
            float bv = bs[s][wid];
            s0 += Mtri[b0 + s] * bv;
            s1 += Mtri[b1 + s] * bv;
            s2 += Mtri[b2 + s] * bv;
            s3 += Mtri[b3 + s] * bv;
        }
#pragma unroll
        for (int o = 16; o > 0; o >>= 1) {
            s0 += __shfl_xor_sync(0xffffffffu, s0, o);
            s1 += __shfl_xor_sync(0xffffffffu, s1, o);
            s2 += __shfl_xor_sync(0xffffffffu, s2, o);
            s3 += __shfl_xor_sync(0xffffffffu, s3, o);
        }
        if (lane == 0) {
            float v0 = bs[r][wid] - s0;
            float v1 = bs[r + 1][wid] - s1 - Mtri[b1 + r] * v0;
            float v2 = bs[r + 2][wid] - s2 - Mtri[b2 + r] * v0 - Mtri[b2 + r + 1] * v1;
            float v3 = bs[r + 3][wid] - s3 - Mtri[b3 + r] * v0 - Mtri[b3 + r + 1] * v1
                                          - Mtri[b3 + r + 2] * v2;
            bs[r][wid] = v0; bs[r + 1][wid] = v1;
            bs[r + 2][wid] = v2; bs[r + 3][wid] = v3;
        }
        __syncwarp();
    }
    __syncthreads();

    {
        int r = tid >> 1, c = (tid & 1) * 4;
        float beta = g_beta[h * TT + chunk * CH + r];
        size_t idx = bo + (size_t)r * TT + j0 + c;
        float v0 = bs[r][c], v1 = bs[r][c + 1], v2 = bs[r][c + 2], v3 = bs[r][c + 3];
        unsigned hw, lw;
        split2pair(v0, v1, hw, lw);
        *(unsigned*)&g_bms[idx] = hw; *(unsigned*)&g_bms[PLT + idx] = lw;
        split2pair(v2, v3, hw, lw);
        *(unsigned*)&g_bms[idx + 2] = hw; *(unsigned*)&g_bms[PLT + idx + 2] = lw;
        split2pair(v0 * beta, v1 * beta, hw, lw);
        *(unsigned*)&g_bts[idx] = hw; *(unsigned*)&g_bts[PLT + idx] = lw;
        split2pair(v2 * beta, v3 * beta, hw, lw);
        *(unsigned*)&g_bts[idx + 2] = hw; *(unsigned*)&g_bts[PLT + idx + 2] = lw;
    }
}

// ---------------- fused split of all inputs into bf16 planes -----------------
__global__ void split_all(const float* __restrict__ x,
                          const float* __restrict__ Wq, const float* __restrict__ Wk,
                          const float* __restrict__ Wv, const float* __restrict__ Ww,
                          const float* __restrict__ Wo)
{
    const int b = blockIdx.x;
    if (b < 2048) {
        size_t i = ((size_t)b * 256 + threadIdx.x) * 4;
        float4 v = *(const float4*)(x + i);
        unsigned h01, l01, h23, l23;
        split2pair(v.x, v.y, h01, l01);
        split2pair(v.z, v.w, h23, l23);
        uint2 hh = {h01, h23}, ll = {l01, l23};
        *(uint2*)&g_xs[i] = hh;
        *(uint2*)&g_xs[PLD + i] = ll;
    } else if (b < 6144) {
        const int wsel = (b - 2048) >> 10;
        const float* W = (wsel == 0) ? Wq : (wsel == 1) ? Wk : (wsel == 2) ? Wv : Ww;
        const int colOfs = wsel * 1024;
        int i = ((b - 2048) & 1023) * 256 + threadIdx.x;
        int e = i * 4;
        int r = e >> 10, c = e & 1023;
        float4 v = *(const float4*)(W + (size_t)r * 1024 + c);
        unsigned h01, l01, h23, l23;
        split2pair(v.x, v.y, h01, l01);
        split2pair(v.z, v.w, h23, l23);
        size_t dst = (size_t)r * 4096 + colOfs + c;
        uint2 hh = {h01, h23}, ll = {l01, l23};
        *(uint2*)&g_W4s[dst] = hh;
        *(uint2*)&g_W4s[PLW + dst] = ll;
    } else {
        size_t i = ((size_t)(b - 6144) * 256 + threadIdx.x) * 4;
        float4 v = *(const float4*)(Wo + i);
        unsigned h01, l01, h23, l23;
        split2pair(v.x, v.y, h01, l01);
        split2pair(v.z, v.w, h23, l23);
        uint2 hh = {h01, h23}, ll = {l01, l23};
        *(uint2*)&g_Wos[i] = hh;
        *(uint2*)&g_Wos[PLO + i] = ll;
    }
}

// ---------------- reduce 4 split-K partials into O planes (row-half) ---------
__global__ void reduce_pv(size_t ofs)
{
    size_t i = ofs + ((size_t)blockIdx.x * 256 + threadIdx.x) * 4;
    float4 a = *(const float4*)(g_raw + i);
    float4 b = *(const float4*)(g_raw + i + PLD);
    float4 c = *(const float4*)(g_raw + i + 2 * PLD);
    float4 d = *(const float4*)(g_raw + i + 3 * PLD);
    float4 o = {a.x + b.x + c.x + d.x, a.y + b.y + c.y + d.y,
                a.z + b.z + c.z + d.z, a.w + b.w + c.w + d.w};
    unsigned h01, l01, h23, l23;
    split2pair(o.x, o.y, h01, l01);
    split2pair(o.z, o.w, h23, l23);
    uint2 hh = {h01, h23}, ll = {l01, l23};
    *(uint2*)&g_Os[i] = hh;
    *(uint2*)&g_Os[PLD + i] = ll;
}

// ---------------- prep: rms(q,k), v, conv+silu+l2norm w -> bf16 planes -------
__device__ __forceinline__ float block_reduce_64(float v, float* sh)
{
    int tid = threadIdx.x;
    sh[tid] = v; __syncthreads();
    for (int s = 32; s > 0; s >>= 1) {
        if (tid < s) sh[tid] += sh[tid + s];
        __syncthreads();
    }
    float r = sh[0]; __syncthreads();
    return r;
}

__global__ void prep_kernel(const float* __restrict__ qn_w,
                            const float* __restrict__ kn_w,
                            const float* __restrict__ convw)
{
    const int t = blockIdx.x, h = blockIdx.y;
    const int c0 = threadIdx.x * 2;
    __shared__ float sh[64];
    const int col = h * HD + c0;
    const size_t rowb = (size_t)t * 4096;
    const size_t out = ((size_t)h * TT + t) * HD + c0;
    unsigned hw, lw;

    float q0 = g_raw[rowb + col], q1 = g_raw[rowb + col + 1];
    float s = block_reduce_64(q0 * q0 + q1 * q1, sh);
    float rq = rsqrtf(s * (1.0f / HD) + 1e-6f);
    split2pair(q0 * rq * qn_w[c0], q1 * rq * qn_w[c0 + 1], hw, lw);
    *(unsigned*)&g_qs[out] = hw; *(unsigned*)&g_qs[PLQ + out] = lw;

    float k0 = g_raw[rowb + 1024 + col], k1 = g_raw[rowb + 1024 + col + 1];
    s = block_reduce_64(k0 * k0 + k1 * k1, sh);
    float rk = rsqrtf(s * (1.0f / HD) + 1e-6f);
    split2pair(k0 * rk * kn_w[c0], k1 * rk * kn_w[c0 + 1], hw, lw);
    *(unsigned*)&g_ks[out] = hw; *(unsigned*)&g_ks[PLQ + out] = lw;

    split2pair(g_raw[rowb + 2048 + col], g_raw[rowb + 2048 + col + 1], hw, lw);
    *(unsigned*)&g_vs[out] = hw; *(unsigned*)&g_vs[PLQ + out] = lw;

    float w0 = 0.0f, w1 = 0.0f;
#pragma unroll
    for (int tap = 0; tap < KC; tap++) {
        int tt = t - (KC - 1) + tap;
        if (tt >= 0) {
            w0 += g_raw[(size_t)tt * 4096 + 3072 + col] * convw[col * KC + tap];
            w1 += g_raw[(size_t)tt * 4096 + 3072 + col + 1] * convw[(col + 1) * KC + tap];
        }
    }
    w0 = w0 / (1.0f + __expf(-w0));
    w1 = w1 / (1.0f + __expf(-w1));
    s = block_reduce_64(w0 * w0 + w1 * w1, sh);
    float rw = rsqrtf(s + 1e-6f);
    split2pair(w0 * rw, w1 * rw, hw, lw);
    *(unsigned*)&g_ws2[out] = hw; *(unsigned*)&g_ws2[PLQ + out] = lw;
}

// ---------------- beta = 2*sigmoid(x@Wbeta), gpre = x@Wg --------------------
__global__ void betag_kernel(const float* __restrict__ x,
                             const float* __restrict__ Wbeta,
                             const float* __restrict__ Wg)
{
    const int t = blockIdx.x;
    const int tid = threadIdx.x;
    const int wid = tid >> 5, lane = tid & 31;
    const float* xr = x + (size_t)t * DD;
    float sb = 0.0f, sg = 0.0f;
    for (int dd = lane; dd < DD; dd += 32) {
        float xv = xr[dd];
        sb += xv * Wbeta[dd * NH + wid];
        sg += xv * Wg[dd * NH + wid];
    }
#pragma unroll
    for (int o = 16; o > 0; o >>= 1) {
        sb += __shfl_down_sync(0xffffffffu, sb, o);
        sg += __shfl_down_sync(0xffffffffu, sg, o);
    }
    if (lane == 0) {
        g_beta[wid * TT + t] = 2.0f / (1.0f + __expf(-sb));
        g_gpre[wid * TT + t] = sg;
    }
}

// ---------------- G = cumsum(log_sigmoid) -- parallel block scan per head ----
__global__ void cumsum_kernel()     // grid = NH, 512 threads, 4 elems/thread
{
    const int h = blockIdx.x;
    const int tid = threadIdx.x, lane = tid & 31, wrp = tid >> 5;
    __shared__ float wsum[16];
    float v[4];
    float run = 0.0f;
#pragma unroll
    for (int u = 0; u < 4; u++) {
        float x = g_gpre[h * TT + tid * 4 + u];
        float ls = fminf(x, 0.0f) - log1pf(__expf(-fabsf(x)));
        run += ls;
        v[u] = run;
    }
    const float tmine = run;
    float tot = run;
#pragma unroll
    for (int o = 1; o < 32; o <<= 1) {
        float t = __shfl_up_sync(0xffffffffu, tot, o);
        if (lane >= o) tot += t;
    }
    if (lane == 31) wsum[wrp] = tot;
    __syncthreads();
    if (wrp == 0) {
        float w = (lane < 16) ? wsum[lane] : 0.0f;
#pragma unroll
        for (int o = 1; o < 16; o <<= 1) {
            float t = __shfl_up_sync(0xffffffffu, w, o);
            if (lane >= o) w += t;
        }
        if (lane < 16) wsum[lane] = w;
    }
    __syncthreads();
    float off = (tot - tmine) + (wrp > 0 ? wsum[wrp - 1] : 0.0f);
#pragma unroll
    for (int u = 0; u < 4; u++)
        g_G[h * TT + tid * 4 + u] = v[u] + off;
}

// ---------------- masked softmax; row-half via rowOfs ------------------------
__global__ void softmax_kernel(int rowOfs)
{
    const int t = blockIdx.x + rowOfs, h = blockIdx.y;
    const size_t ro = ((size_t)h * TT + t) * TT;
    const float* row = g_A + ro;
    const float* Gh = g_G + h * TT;
    const float Gt = Gh[t];
    const int n = t + 1;
    const int tid = threadIdx.x;
    __shared__ float buf[TT];
    __shared__ float red[256];

    float m = -1e30f;
    for (int j = tid; j < n; j += 256) {
        float l = row[j] * ATT_SCALE + Gt - Gh[j];
        buf[j] = l;
        m = fmaxf(m, l);
    }
    red[tid] = m; __syncthreads();
    for (int s = 128; s > 0; s >>= 1) {
        if (tid < s) red[tid] = fmaxf(red[tid], red[tid + s]);
        __syncthreads();
    }
    m = red[0]; __syncthreads();

    float sum = 0.0f;
    for (int j = tid; j < n; j += 256) sum += __expf(buf[j] - m);
    red[tid] = sum; __syncthreads();
    for (int s = 128; s > 0; s >>= 1) {
        if (tid < s) red[tid] += red[tid + s];
        __syncthreads();
    }
    const float inv = 1.0f / red[0];

    for (int jj = tid; jj < TT / 2; jj += 256) {
        int j0 = jj * 2;
        float p0 = (j0 < n) ? __expf(buf[j0] - m) * inv : 0.0f;
        float p1 = (j0 + 1 < n) ? __expf(buf[j0 + 1] - m) * inv : 0.0f;
        unsigned hw, lw;
        split2pair(p0, p1, hw, lw);
        *(unsigned*)&g_Ps[ro + j0] = hw;
        *(unsigned*)&g_Ps[PLT + ro + j0] = lw;
    }
}

// ---------------------------------------------------------------------------
extern "C" void kernel_launch(void* const* d_in, const int* in_sizes, int n_in,
                              void* d_out, int out_size)
{
    const float* x     = (const float*)d_in[0];
    const float* Wq    = (const float*)d_in[1];
    const float* Wk    = (const float*)d_in[2];
    const float* Wv    = (const float*)d_in[3];
    const float* Ww    = (const float*)d_in[4];
    const float* Wbeta = (const float*)d_in[5];
    const float* Wg    = (const float*)d_in[6];
    const float* Wo    = (const float*)d_in[7];
    const float* convw = (const float*)d_in[8];
    const float* qnw   = (const float*)d_in[9];
    const float* knw   = (const float*)d_in[10];
    float* out = (float*)d_out;

    cudaFuncSetAttribute(mma_nn_b, cudaFuncAttributeMaxDynamicSharedMemorySize, SMNN);
    cudaFuncSetAttribute(mma_nt_b, cudaFuncAttributeMaxDynamicSharedMemorySize, SMNT);

    static cudaStream_t s2 = nullptr, s3 = nullptr;
    static cudaEvent_t evF0 = nullptr, evS0 = nullptr, evF1 = nullptr, evS1 = nullptr;
    static cudaEvent_t evTL = nullptr, evOutL = nullptr;
    static cudaEvent_t evSol[NCHUNK] = {};
    static cudaEvent_t evRest[NCHUNK] = {};
    if (!s2) {
        int loPri, hiPri;                      // hiPri = most-negative = greatest
        cudaDeviceGetStreamPriorityRange(&loPri, &hiPri);
        cudaStreamCreateWithPriority(&s2, cudaStreamNonBlocking, hiPri);
        cudaStreamCreateWithPriority(&s3, cudaStreamNonBlocking, hiPri);
        cudaEventCreateWithFlags(&evF0, cudaEventDisableTiming);
        cudaEventCreateWithFlags(&evS0, cudaEventDisableTiming);
        cudaEventCreateWithFlags(&evF1, cudaEventDisableTiming);
        cudaEventCreateWithFlags(&evS1, cudaEventDisableTiming);
        cudaEventCreateWithFlags(&evTL, cudaEventDisableTiming);
        cudaEventCreateWithFlags(&evOutL, cudaEventDisableTiming);
        for (int i = 0; i < NCHUNK; i++) {
            cudaEventCreateWithFlags(&evSol[i], cudaEventDisableTiming);
            cudaEventCreateWithFlags(&evRest[i], cudaEventDisableTiming);
        }
    }

    float *raw, *A, *bm, *beta;
    __nv_bfloat16 *xs, *W4s, *Wos, *qs, *ks, *vs, *ws, *QWs, *Mws, *Ps, *bms, *bts, *Os;
    cudaGetSymbolAddress((void**)&raw, g_raw);
    cudaGetSymbolAddress((void**)&A, g_A);
    cudaGetSymbolAddress((void**)&bm, g_bm);
    cudaGetSymbolAddress((void**)&beta, g_beta);
    cudaGetSymbolAddress((void**)&xs, g_xs);
    cudaGetSymbolAddress((void**)&W4s, g_W4s);
    cudaGetSymbolAddress((void**)&Wos, g_Wos);
    cudaGetSymbolAddress((void**)&qs, g_qs);
    cudaGetSymbolAddress((void**)&ks, g_ks);
    cudaGetSymbolAddress((void**)&vs, g_vs);
    cudaGetSymbolAddress((void**)&ws, g_ws2);
    cudaGetSymbolAddress((void**)&QWs, g_QWs);
    cudaGetSymbolAddress((void**)&Mws, g_Mws);
    cudaGetSymbolAddress((void**)&Ps, g_Ps);
    cudaGetSymbolAddress((void**)&bms, g_bms);
    cudaGetSymbolAddress((void**)&bts, g_bts);
    cudaGetSymbolAddress((void**)&Os, g_Os);

    const long long TTTT = (long long)TT * TT;

    // fork A: betag+cumsum on side stream, overlapping split+proj on main
    cudaEventRecord(evF0, 0);
    cudaStreamWaitEvent(s2, evF0, 0);
    betag_kernel<<<TT, 256, 0, s2>>>(x, Wbeta, Wg);
    cumsum_kernel<<<NH, 512, 0, s2>>>();
    cudaEventRecord(evS0, s2);

    split_all<<<7168, 256>>>(x, Wq, Wk, Wv, Ww, Wo);
    mma_nn_b<<<dim3(4 * DD / BN, TT / BM, 1), 256, SMNN>>>(
        xs, xs + PLD, W4s, W4s + PLW, raw, DD, DD, 4 * DD, 4 * DD, 0, 0, 0, 0, 0);
    prep_kernel<<<dim3(TT, NH), 64>>>(qnw, knw, convw);
    cudaStreamWaitEvent(0, evS0, 0);      // beta/G ready

    const dim3 gNT(TT / BN, TT / BM, NH);
    // solve-chain inputs first
    mma_nt_b<<<gNT, 256, SMNT>>>(ws, ws + PLQ, ks, ks + PLQ, bm, nullptr, nullptr, nullptr, 2);   // rhs
    mma_nt_b<<<gNT, 256, SMNT>>>(ws, ws + PLQ, ws, ws + PLQ, nullptr, Mws, Mws + PLT, beta, 3);   // Mw

    // fork B: lookahead solve chain — s2 = critical (narrow update + solve),
    // s3 = off-critical rest-of-trailing updates. Both high priority so their
    // small kernels dispatch ahead of the wide NT/tri tiles on the main stream.
    cudaEventRecord(evF1, 0);
    cudaStreamWaitEvent(s2, evF1, 0);
    cudaStreamWaitEvent(s3, evF1, 0);
    chunk_solve<<<dim3(16, NH), 256, 0, s2>>>(0);
    cudaEventRecord(evSol[0], s2);
    for (int c = 0; c < NCHUNK - 1; c++) {
        size_t moN = (size_t)(c + 1) * CH * TT + (size_t)c * CH;
        size_t bo  = (size_t)c * CH * TT;
        if (c >= 1) cudaStreamWaitEvent(s2, evRest[c - 1], 0);
        mma_nn_b<<<dim3(c + 1, 1, NH), 256, SMNN, s2>>>(
            Mws + moN, Mws + PLT + moN, bms + bo, bms + PLT + bo,
            bm + (size_t)(c + 1) * CH * TT,
            CH, TT, TT, TT, TTTT, TTTT, TTTT, 1, 0);
        chunk_solve<<<dim3((c + 2) * 16, NH), 256, 0, s2>>>(c + 1);
        cudaEventRecord(evSol[c + 1], s2);
        if (c < NCHUNK - 2) {
            size_t moR = (size_t)(c + 2) * CH * TT + (size_t)c * CH;
            cudaStreamWaitEvent(s3, evSol[c], 0);
            mma_nn_b<<<dim3(c + 1, NCHUNK - 2 - c, NH), 256, SMNN, s3>>>(
                Mws + moR, Mws + PLT + moR, bms + bo, bms + PLT + bo,
                bm + (size_t)(c + 2) * CH * TT,
                CH, TT, TT, TT, TTTT, TTTT, TTTT, 1, 0);
            cudaEventRecord(evRest[c], s3);
        }
    }
    cudaEventRecord(evS1, s2);

    // main stream: QK^T and tril(QW^T) overlap the chain
    mma_nt_b<<<gNT, 256, SMNT>>>(qs, qs + PLQ, ks, ks + PLQ, A, nullptr, nullptr, nullptr, 0);     // QK^T
    mma_nt_b<<<gNT, 256, SMNT>>>(qs, qs + PLQ, ws, ws + PLQ, nullptr, QWs, QWs + PLT, nullptr, 1); // tril(QW)
    cudaStreamWaitEvent(0, evS1, 0);      // join: btil ready

    // ---- row-half pipelined epilogue ----
    mma_nn_b<<<dim3(8, 8, NH), 256, SMNN>>>(QWs, QWs + PLT, bts, bts + PLT, A,
                                            TT, TT, TT, TT, TTTT, TTTT, TTTT, 3, 0);
    cudaEventRecord(evTL, 0);
    mma_nn_b<<<dim3(16, 8, NH), 256, SMNN>>>(QWs, QWs + PLT, bts, bts + PLT, A,
                                             TT, TT, TT, TT, TTTT, TTTT, TTTT, 3, 8);

    cudaStreamWaitEvent(s3, evTL, 0);
    softmax_kernel<<<dim3(1024, NH), 256, 0, s3>>>(0);
    mma_nn_b<<<dim3(1, 8, NH * 4), 256, SMNN, s3>>>(
        Ps, Ps + PLT, vs, vs + PLQ, raw, TT, TT, HD, DD,
        TTTT, (long long)TT * HD, HD, 8, 0);
    reduce_pv<<<1024, 256, 0, s3>>>(0);
    mma_nn_b<<<dim3(DD / BN, 8, 1), 256, SMNN, s3>>>(
        Os, Os + PLD, Wos, Wos + PLO, out, DD, DD, DD, DD, 0, 0, 0, 0, 0);
    cudaEventRecord(evOutL, s3);

    softmax_kernel<<<dim3(1024, NH), 256>>>(1024);
    mma_nn_b<<<dim3(1, 8, NH * 4), 256, SMNN>>>(
        Ps, Ps + PLT, vs, vs + PLQ, raw, TT, TT, HD, DD,
        TTTT, (long long)TT * HD, HD, 8, 8);
    reduce_pv<<<1024, 256>>>((size_t)1024 * DD);
    mma_nn_b<<<dim3(DD / BN, 8, 1), 256, SMNN>>>(
        Os, Os + PLD, Wos, Wos + PLO, out, DD, DD, DD, DD, 0, 0, 0, 0, 8);

    cudaStreamWaitEvent(0, evOutL, 0);    // join lower-half pipeline
}